// round 5
// baseline (speedup 1.0000x reference)
#include <cuda_runtime.h>
#include <cuda_bf16.h>

// TTTConv: causal depthwise conv1d (fused conv_output + conv_states)
//   x: (B,N,D) fp32, w: (D,K), bias: (D,);  B=4, N=4096, D=2048, K=4
// d_out = [ conv_output (B,N,D) | conv_states (B,D,K) ]

#define Bc 4
#define Nc 4096
#define Dc 2048
#define Kc 4
#define NT 64          // time steps per thread -> 512 blocks = single resident wave
#define CH 4           // chunk: loads batched 4-deep for MLP
#define DV (Dc / 4)    // float4 groups along D = 512

__global__ void __launch_bounds__(256, 4) ttt_conv_fused(
    const float* __restrict__ x,
    const float* __restrict__ w,
    const float* __restrict__ bias,
    float* __restrict__ out,
    float* __restrict__ states)
{
    int tid  = blockIdx.x * blockDim.x + threadIdx.x;
    int dvec = tid % DV;                 // float4 group along D
    int nt   = (tid / DV) % (Nc / NT);   // time tile
    int b    = tid / (DV * (Nc / NT));   // batch
    int d    = dvec * 4;
    int n0   = nt * NT;

    float4 wv0 = ((const float4*)w)[d + 0];
    float4 wv1 = ((const float4*)w)[d + 1];
    float4 wv2 = ((const float4*)w)[d + 2];
    float4 wv3 = ((const float4*)w)[d + 3];
    float4 bv  = ((const float4*)bias)[dvec];

    // 32-bit byte offsets (tensors << 4GB): base points at (b, n0, d)
    unsigned base = ((unsigned)b * Nc * Dc + (unsigned)n0 * Dc + (unsigned)d) * 4u;
    const char* xp = (const char*)x   + base;
    char*       op = (char*)      out + base;
    const unsigned ROW = Dc * 4u;  // byte stride per time step

    // Sliding window: x at n-3, n-2, n-1
    float4 xm3, xm2, xm1;
    if (n0 == 0) {
        xm3 = make_float4(0.f, 0.f, 0.f, 0.f);
        xm2 = xm3;
        xm1 = xm3;
    } else {
        xm3 = *(const float4*)(xp - 3 * ROW);
        xm2 = *(const float4*)(xp - 2 * ROW);
        xm1 = *(const float4*)(xp - 1 * ROW);
    }

    for (int c = 0; c < NT / CH; ++c) {
        // ---- batch loads: CH independent LDG.128 front-to-front ----
        float4 buf[CH];
#pragma unroll
        for (int i = 0; i < CH; ++i)
            buf[i] = *(const float4*)(xp + (unsigned)i * ROW);

        // ---- compute + store inline (stores are fire-and-forget) ----
#pragma unroll
        for (int i = 0; i < CH; ++i) {
            float4 xc = buf[i];
            float4 r;
            r.x = fmaf(xm3.x, wv0.x, fmaf(xm2.x, wv0.y, fmaf(xm1.x, wv0.z, fmaf(xc.x, wv0.w, bv.x))));
            r.y = fmaf(xm3.y, wv1.x, fmaf(xm2.y, wv1.y, fmaf(xm1.y, wv1.z, fmaf(xc.y, wv1.w, bv.y))));
            r.z = fmaf(xm3.z, wv2.x, fmaf(xm2.z, wv2.y, fmaf(xm1.z, wv2.z, fmaf(xc.z, wv2.w, bv.z))));
            r.w = fmaf(xm3.w, wv3.x, fmaf(xm2.w, wv3.y, fmaf(xm1.w, wv3.z, fmaf(xc.w, wv3.w, bv.w))));
            *(float4*)(op + (unsigned)i * ROW) = r;
            xm3 = xm2; xm2 = xm1; xm1 = xc;
        }
        xp += CH * ROW;
        op += CH * ROW;
    }

    // Last time-tile threads emit conv_states (B, D, K): k contiguous ->
    // one float4 per channel. Window regs hold x[N-3..N-1]; reload x[N-4]
    // (L2 hit — just streamed by this thread). xp now points at row N.
    if (n0 == Nc - NT) {
        float4 a = *(const float4*)(xp - 4 * ROW);
        float4* sb = (float4*)states + (size_t)b * Dc + d;
        sb[0] = make_float4(a.x, xm3.x, xm2.x, xm1.x);
        sb[1] = make_float4(a.y, xm3.y, xm2.y, xm1.y);
        sb[2] = make_float4(a.z, xm3.z, xm2.z, xm1.z);
        sb[3] = make_float4(a.w, xm3.w, xm2.w, xm1.w);
    }
}

extern "C" void kernel_launch(void* const* d_in, const int* in_sizes, int n_in,
                              void* d_out, int out_size)
{
    const float* x    = (const float*)d_in[0];
    const float* w    = (const float*)d_in[1];
    const float* bias = (const float*)d_in[2];
    float* out    = (float*)d_out;
    float* states = out + (size_t)Bc * Nc * Dc;

    int total = Bc * (Nc / NT) * DV;   // 131072 threads -> 512 blocks
    ttt_conv_fused<<<total / 256, 256>>>(x, w, bias, out, states);
}

// round 7
// speedup vs baseline: 1.0498x; 1.0498x over previous
#include <cuda_runtime.h>
#include <cuda_bf16.h>

// TTTConv: causal depthwise conv1d (fused conv_output + conv_states)
//   x: (B,N,D) fp32, w: (D,K), bias: (D,);  B=4, N=4096, D=2048, K=4
// d_out = [ conv_output (B,N,D) | conv_states (B,D,K) ]

#define Bc 4
#define Nc 4096
#define Dc 2048
#define Kc 4
#define NT 32          // time steps per thread
#define CH 8           // chunk: loads batched 8-deep for MLP
#define DV (Dc / 4)    // float4 groups along D = 512

__global__ void __launch_bounds__(256, 3) ttt_conv_fused(
    const float* __restrict__ x,
    const float* __restrict__ w,
    const float* __restrict__ bias,
    float* __restrict__ out,
    float* __restrict__ states)
{
    int tid  = blockIdx.x * blockDim.x + threadIdx.x;
    int dvec = tid % DV;                 // float4 group along D
    int nt   = (tid / DV) % (Nc / NT);   // time tile
    int b    = tid / (DV * (Nc / NT));   // batch
    int d    = dvec * 4;
    int n0   = nt * NT;

    float4 wv0 = ((const float4*)w)[d + 0];
    float4 wv1 = ((const float4*)w)[d + 1];
    float4 wv2 = ((const float4*)w)[d + 2];
    float4 wv3 = ((const float4*)w)[d + 3];
    float4 bv  = ((const float4*)bias)[dvec];

    // 32-bit byte offsets (tensors << 4GB): base points at (b, n0, d)
    unsigned base = ((unsigned)b * Nc * Dc + (unsigned)n0 * Dc + (unsigned)d) * 4u;
    const char* xp = (const char*)x   + base;
    char*       op = (char*)      out + base;
    const unsigned ROW = Dc * 4u;  // byte stride per time step

    // Sliding window: x at n-3, n-2, n-1
    float4 xm3, xm2, xm1;
    if (n0 == 0) {
        xm3 = make_float4(0.f, 0.f, 0.f, 0.f);
        xm2 = xm3;
        xm1 = xm3;
    } else {
        xm3 = *(const float4*)(xp - 3 * ROW);
        xm2 = *(const float4*)(xp - 2 * ROW);
        xm1 = *(const float4*)(xp - 1 * ROW);
    }

    for (int c = 0; c < NT / CH; ++c) {
        // ---- batch loads: CH independent LDG.128 front-to-front ----
        float4 buf[CH];
#pragma unroll
        for (int i = 0; i < CH; ++i)
            buf[i] = *(const float4*)(xp + (unsigned)i * ROW);

        // ---- compute + store inline (stores are fire-and-forget) ----
#pragma unroll
        for (int i = 0; i < CH; ++i) {
            float4 xc = buf[i];
            float4 r;
            r.x = fmaf(xm3.x, wv0.x, fmaf(xm2.x, wv0.y, fmaf(xm1.x, wv0.z, fmaf(xc.x, wv0.w, bv.x))));
            r.y = fmaf(xm3.y, wv1.x, fmaf(xm2.y, wv1.y, fmaf(xm1.y, wv1.z, fmaf(xc.y, wv1.w, bv.y))));
            r.z = fmaf(xm3.z, wv2.x, fmaf(xm2.z, wv2.y, fmaf(xm1.z, wv2.z, fmaf(xc.z, wv2.w, bv.z))));
            r.w = fmaf(xm3.w, wv3.x, fmaf(xm2.w, wv3.y, fmaf(xm1.w, wv3.z, fmaf(xc.w, wv3.w, bv.w))));
            *(float4*)(op + (unsigned)i * ROW) = r;
            xm3 = xm2; xm2 = xm1; xm1 = xc;
        }
        xp += CH * ROW;
        op += CH * ROW;
    }

    // Last time-tile threads emit conv_states (B, D, K): k contiguous ->
    // one float4 per channel. Window regs hold x[N-3..N-1]; reload x[N-4]
    // (L2 hit — just streamed by this thread). xp now points at row n0+NT.
    if (n0 == Nc - NT) {
        float4 a = *(const float4*)(xp - 4 * ROW);
        float4* sb = (float4*)states + (size_t)b * Dc + d;
        sb[0] = make_float4(a.x, xm3.x, xm2.x, xm1.x);
        sb[1] = make_float4(a.y, xm3.y, xm2.y, xm1.y);
        sb[2] = make_float4(a.z, xm3.z, xm2.z, xm1.z);
        sb[3] = make_float4(a.w, xm3.w, xm2.w, xm1.w);
    }
}

extern "C" void kernel_launch(void* const* d_in, const int* in_sizes, int n_in,
                              void* d_out, int out_size)
{
    const float* x    = (const float*)d_in[0];
    const float* w    = (const float*)d_in[1];
    const float* bias = (const float*)d_in[2];
    float* out    = (float*)d_out;
    float* states = out + (size_t)Bc * Nc * Dc;

    int total = Bc * (Nc / NT) * DV;   // 262144 threads -> 1024 blocks
    ttt_conv_fused<<<total / 256, 256>>>(x, w, bias, out, states);
}